// round 5
// baseline (speedup 1.0000x reference)
#include <cuda_runtime.h>
#include <math.h>
#include <float.h>

// Problem constants: B=8, Z=4, X=32, Y=32, N=4096
#define NPTS   4096
#define NB     8
#define TILES  16
#define PPTILE (NPTS / TILES)     // 256 points per CTA
#define T      512
#define NW     (T / 32)
#define MAXK   16
#define REGN   8                  // warp fast path holds 32*8 = 256 survivors
#define CUT    2.0f

// dynamic smem: staging (2*2560 floats) unioned with survivor arrays (5*4096)
#define SMEM_BYTES (20480 * 4)

// Per-batch global scratch (reset by elected CTA at end of every run)
__device__ unsigned long long gMax[NB];          // packed (conf_bits<<32)|(4096-idx)
__device__ int gnP[NB], gnT[NB], gDone[NB];
__device__ float4 gP[NB][NPTS];                  // compact pred: x,y,z (norm), conf
__device__ int    gPi[NB][NPTS];                 // compact pred original idx
__device__ float4 gT[NB][NPTS];                  // compact targ: x,y,z (real), idx bits

__device__ __forceinline__ float row_angle(float ax, float ay, float az,
                                           float bx, float by, float bz) {
    float na = sqrtf(ax * ax + ay * ay + az * az);
    float nb = sqrtf(bx * bx + by * by + bz * bz);
    float c = (ax * bx + ay * by + az * bz) / (na * nb);
    c = fminf(1.0f, fmaxf(-1.0f, c));
    return (acosf(c) / 3.14159265358979323846f) * 180.0f;
}

__global__ __launch_bounds__(T, 1)
void mol_kernel(const float* __restrict__ pred,
                const float* __restrict__ targ,
                float* __restrict__ out) {
    extern __shared__ float sm[];
    // staging view (phase A)
    float* SP = sm;                         // [2560] raw pred slice
    float* ST = sm + 2560;                  // [2560] raw targ slice
    // survivor view (phase B, after staging is dead)
    float* svX = sm;                        // [4096]
    float* svY = sm + 4096;
    float* svZ = sm + 8192;
    float* svC = sm + 12288;
    int*   svI = (int*)(sm + 16384);

    __shared__ unsigned long long wMax[8];
    __shared__ int wOffP[8], wOffT[8];
    __shared__ float wv[NW];
    __shared__ int wiA[NW], wsA[NW];
    __shared__ int sCntP, sCntT, sBaseP, sBaseT, sLast, sS, sK, sCont;
    __shared__ float pick[3], sSelX, sSelY, sSelZ;
    __shared__ int   kId[MAXK];
    __shared__ float kRX[MAXK], kRY[MAXK], kRZ[MAXK];
    __shared__ int   sMatch[MAXK], sHit[MAXK];
    __shared__ float sAngA[MAXK];

    const int tid = threadIdx.x;
    const int lane = tid & 31;
    const int warp = tid >> 5;
    const unsigned lt = (1u << lane) - 1u;
    const int b = blockIdx.x >> 4;          // 16 tiles per batch
    const int tile = blockIdx.x & 15;

    // ================= Phase A: load slice, compact actives, partial argmax ====
    {
        const float4* gp4 = (const float4*)(pred + ((size_t)b * NPTS + tile * PPTILE) * 10);
        const float4* gt4 = (const float4*)(targ + ((size_t)b * NPTS + tile * PPTILE) * 10);
        float4* SP4 = (float4*)SP;
        float4* ST4 = (float4*)ST;
        #pragma unroll
        for (int i = tid; i < PPTILE * 10 / 4; i += T) {   // 640 float4 each
            SP4[i] = gp4[i];
            ST4[i] = gt4[i];
        }
        if (tid == 0) { sCntP = 0; sCntT = 0; }
        __syncthreads();

        unsigned mP = 0, mT = 0;
        bool pa = false, ta = false;
        float px = 0, py = 0, pz = 0, pc = 0, tx = 0, ty = 0, tz = 0;
        int n = 0;
        if (warp < 8) {                      // threads 0..255 parse one point each
            int loc = tid;
            n = tile * PPTILE + loc;
            float fz = (float)(n >> 10), fx = (float)((n >> 5) & 31), fy = (float)(n & 31);
            const float* p = SP + loc * 10;
            const float* t = ST + loc * 10;
            pc = p[0];
            pa = pc > 0.0f;                               // sigmoid>0.5 <=> raw>0
            px = (p[1] + fz) * 0.25f;                     // /Z=4 exact
            py = (p[2] + fx) * 0.03125f;                  // /X=32 exact
            pz = (p[3] + fy) * 0.03125f;                  // /Y=32 exact
            ta = t[0] > 0.5f;
            tx = ((t[1] + fz) * 0.25f) * 25.0f;           // real coords
            ty = ((t[2] + fx) * 0.03125f) * 25.0f;
            tz = ((t[3] + fy) * 0.03125f) * 4.0f;
            mP = __ballot_sync(0xffffffffu, pa);
            mT = __ballot_sync(0xffffffffu, ta);
            if (lane == 0) {
                wOffP[warp] = atomicAdd(&sCntP, __popc(mP));
                wOffT[warp] = atomicAdd(&sCntT, __popc(mT));
            }
            // packed argmax: higher conf wins; tie -> lower original idx
            unsigned long long pk = pa
                ? ((((unsigned long long)__float_as_uint(pc)) << 32) |
                   (unsigned long long)(NPTS - n))
                : 0ull;
            #pragma unroll
            for (int o = 16; o; o >>= 1) {
                unsigned long long q = __shfl_down_sync(0xffffffffu, pk, o);
                if (q > pk) pk = q;
            }
            if (lane == 0) wMax[warp] = pk;
        }
        __syncthreads();
        if (tid == 0) {
            sBaseP = atomicAdd(&gnP[b], sCntP);
            sBaseT = atomicAdd(&gnT[b], sCntT);
            unsigned long long m = wMax[0];
            #pragma unroll
            for (int w = 1; w < 8; w++) if (wMax[w] > m) m = wMax[w];
            if (m) atomicMax(&gMax[b], m);
        }
        __syncthreads();
        if (warp < 8) {
            if (pa) {
                int s = sBaseP + wOffP[warp] + __popc(mP & lt);
                gP[b][s] = make_float4(px, py, pz, pc);
                gPi[b][s] = n;
            }
            if (ta) {
                int s = sBaseT + wOffT[warp] + __popc(mT & lt);
                gT[b][s] = make_float4(tx, ty, tz, __int_as_float(n));
            }
        }
    }
    __threadfence();
    __syncthreads();
    if (tid == 0) {
        int old = atomicAdd(&gDone[b], 1);
        sLast = (old == TILES - 1) ? 1 : 0;
    }
    __syncthreads();
    if (!sLast) return;

    // ================= Phase B: elected CTA finishes batch b ====================
    __threadfence();
    if (tid == 0) {
        sCntP = atomicAdd(&gnP[b], 0);
        sCntT = atomicAdd(&gnT[b], 0);
        unsigned long long mx = atomicAdd(&gMax[b], 0ull);
        if (mx == 0ull) {
            sK = 0;
        } else {
            int idx = NPTS - (int)(mx & 0xffffffffu);
            const float* p = pred + ((size_t)b * NPTS + idx) * 10;
            float fz = (float)(idx >> 10), fx = (float)((idx >> 5) & 31), fy = (float)(idx & 31);
            float qx = (p[1] + fz) * 0.25f;
            float qy = (p[2] + fx) * 0.03125f;
            float qz = (p[3] + fy) * 0.03125f;
            pick[0] = qx; pick[1] = qy; pick[2] = qz;
            kId[0] = idx;
            kRX[0] = qx * 25.0f; kRY[0] = qy * 25.0f; kRZ[0] = qz * 4.0f;
            sK = 1;
        }
        sS = 0;
    }
    __syncthreads();
    const int np = sCntP;
    const int nt = sCntT;

    // ---- survivors of pick0's suppression ball (normalized coords) ----
    if (sK > 0) {
        float cx = pick[0], cy = pick[1], cz = pick[2];
        for (int e = tid; e < np; e += T) {
            float4 q = gP[b][e];
            float d0 = q.x - cx, d1 = q.y - cy, d2 = q.z - cz;
            float ss = (d0 * d0 + d1 * d1) + d2 * d2;
            if (sqrtf(ss) >= CUT) {
                int s = atomicAdd(&sS, 1);
                svX[s] = q.x; svY[s] = q.y; svZ[s] = q.z; svC[s] = q.w;
                svI[s] = gPi[b][e];
            }
        }
        __syncthreads();
        const int S = sS;

        if (S > 0 && S <= 32 * REGN) {
            // fast path: warp 0 runs all remaining rounds in registers
            if (warp == 0) {
                float c8[REGN], x8[REGN], y8[REGN], z8[REGN];
                int i8[REGN];
                #pragma unroll
                for (int j = 0; j < REGN; j++) {
                    int e = lane + j * 32;
                    c8[j] = -FLT_MAX; i8[j] = 0x7fffffff;
                    x8[j] = 0.0f; y8[j] = 0.0f; z8[j] = 0.0f;
                    if (e < S) {
                        c8[j] = svC[e]; x8[j] = svX[e]; y8[j] = svY[e]; z8[j] = svZ[e];
                        i8[j] = svI[e];
                    }
                }
                int K = 1;
                while (K < MAXK) {
                    float bv = -FLT_MAX, bx = 0.0f, by = 0.0f, bz = 0.0f;
                    int bk = 0x7fffffff;
                    #pragma unroll
                    for (int j = 0; j < REGN; j++) {
                        if (c8[j] > bv || (c8[j] == bv && i8[j] < bk)) {
                            bv = c8[j]; bk = i8[j]; bx = x8[j]; by = y8[j]; bz = z8[j];
                        }
                    }
                    #pragma unroll
                    for (int o = 16; o; o >>= 1) {
                        float v2 = __shfl_xor_sync(0xffffffffu, bv, o);
                        int k2 = __shfl_xor_sync(0xffffffffu, bk, o);
                        float x2 = __shfl_xor_sync(0xffffffffu, bx, o);
                        float y2 = __shfl_xor_sync(0xffffffffu, by, o);
                        float z2 = __shfl_xor_sync(0xffffffffu, bz, o);
                        if (v2 > bv || (v2 == bv && k2 < bk)) {
                            bv = v2; bk = k2; bx = x2; by = y2; bz = z2;
                        }
                    }
                    if (bv == -FLT_MAX) break;
                    if (lane == 0) {
                        kId[K] = bk;
                        kRX[K] = bx * 25.0f; kRY[K] = by * 25.0f; kRZ[K] = bz * 4.0f;
                    }
                    K++;
                    #pragma unroll
                    for (int j = 0; j < REGN; j++) {
                        float d0 = x8[j] - bx, d1 = y8[j] - by, d2 = z8[j] - bz;
                        float ss = (d0 * d0 + d1 * d1) + d2 * d2;
                        if (sqrtf(ss) < CUT) c8[j] = -FLT_MAX;
                    }
                }
                if (lane == 0) sK = K;
            }
            __syncthreads();
        } else if (S > 0) {
            // fallback: block-wide greedy over survivor smem arrays
            for (;;) {
                float bv = -FLT_MAX;
                int bk = 0x7fffffff, bs = -1;
                for (int e = tid; e < S; e += T) {
                    float v = svC[e];
                    if (v != -FLT_MAX) {
                        int id = svI[e];
                        if (v > bv || (v == bv && id < bk)) { bv = v; bk = id; bs = e; }
                    }
                }
                #pragma unroll
                for (int o = 16; o; o >>= 1) {
                    float v2 = __shfl_down_sync(0xffffffffu, bv, o);
                    int k2 = __shfl_down_sync(0xffffffffu, bk, o);
                    int s2 = __shfl_down_sync(0xffffffffu, bs, o);
                    if (v2 > bv || (v2 == bv && k2 < bk)) { bv = v2; bk = k2; bs = s2; }
                }
                if (lane == 0) { wv[warp] = bv; wiA[warp] = bk; wsA[warp] = bs; }
                __syncthreads();
                if (warp == 0) {
                    float v = (lane < NW) ? wv[lane] : -FLT_MAX;
                    int k = (lane < NW) ? wiA[lane] : 0x7fffffff;
                    int s = (lane < NW) ? wsA[lane] : -1;
                    #pragma unroll
                    for (int o = 8; o; o >>= 1) {
                        float v2 = __shfl_down_sync(0xffffffffu, v, o);
                        int k2 = __shfl_down_sync(0xffffffffu, k, o);
                        int s2 = __shfl_down_sync(0xffffffffu, s, o);
                        if (v2 > v || (v2 == v && k2 < k)) { v = v2; k = k2; s = s2; }
                    }
                    if (lane == 0) {
                        if (v == -FLT_MAX || sK >= MAXK) {
                            sCont = 0;
                        } else {
                            int K = sK;
                            kId[K] = k;
                            kRX[K] = svX[s] * 25.0f; kRY[K] = svY[s] * 25.0f;
                            kRZ[K] = svZ[s] * 4.0f;
                            sSelX = svX[s]; sSelY = svY[s]; sSelZ = svZ[s];
                            sK = K + 1;
                            sCont = 1;
                        }
                    }
                }
                __syncthreads();
                if (!sCont) break;
                float cx2 = sSelX, cy2 = sSelY, cz2 = sSelZ;
                for (int e = tid; e < S; e += T) {
                    if (svC[e] != -FLT_MAX) {
                        float d0 = svX[e] - cx2, d1 = svY[e] - cy2, d2 = svZ[e] - cz2;
                        float ss = (d0 * d0 + d1 * d1) + d2 * d2;
                        if (sqrtf(ss) < CUT) svC[e] = -FLT_MAX;
                    }
                }
                __syncthreads();
            }
        }
    }
    __syncthreads();

    // ---- matching: warp k scans compact targets (real coords) for kept k ----
    const int K = sK;
    if (warp < K) {
        float qx = kRX[warp], qy = kRY[warp], qz = kRZ[warp];
        int best = 0x7fffffff;
        for (int e = lane; e < nt; e += 32) {
            float4 q = gT[b][e];
            float d0 = q.x - qx, d1 = q.y - qy, d2 = q.z - qz;
            float ss = (d0 * d0 + d1 * d1) + d2 * d2;
            if (sqrtf(ss) < CUT) {
                int id = __float_as_int(q.w);
                if (id < best) best = id;
            }
        }
        #pragma unroll
        for (int o = 16; o; o >>= 1) {
            int v2 = __shfl_down_sync(0xffffffffu, best, o);
            if (v2 < best) best = v2;
        }
        if (lane == 0) sMatch[warp] = best;
    }
    __syncthreads();

    // ---- angles: K parallel computations (rotation rows, 8B-aligned float2) ----
    if (tid < K) {
        int mt = sMatch[tid];
        if (mt != 0x7fffffff) {
            const float* p = pred + ((size_t)b * NPTS + kId[tid]) * 10 + 4;
            const float* t = targ + ((size_t)b * NPTS + mt) * 10 + 4;
            float2 pa2 = *(const float2*)p;
            float2 pb2 = *(const float2*)(p + 2);
            float2 pc2 = *(const float2*)(p + 4);
            float2 ta2 = *(const float2*)t;
            float2 tb2 = *(const float2*)(t + 2);
            float2 tc2 = *(const float2*)(t + 4);
            float ax = pa2.x, ay = pa2.y, az = pb2.x;
            float bx = pb2.y, by = pc2.x, bz = pc2.y;
            float cx = ay * bz - az * by;
            float cy = az * bx - ax * bz;
            float cz = ax * by - ay * bx;
            float tax = ta2.x, tay = ta2.y, taz = tb2.x;
            float tbx = tb2.y, tby = tc2.x, tbz = tc2.y;
            float tcx = tay * tbz - taz * tby;
            float tcy = taz * tbx - tax * tbz;
            float tcz = tax * tby - tay * tbx;
            sAngA[tid] = row_angle(ax, ay, az, tax, tay, taz)
                       + row_angle(bx, by, bz, tbx, tby, tbz)
                       + row_angle(cx, cy, cz, tcx, tcy, tcz);
            sHit[tid] = 1;
        } else {
            sAngA[tid] = 0.0f;
            sHit[tid] = 0;
        }
    }
    __syncthreads();

    // ---- epilogue + reset scratch for next graph replay ----
    if (tid == 0) {
        int tp = 0;
        float ang = 0.0f;
        for (int k = 0; k < K; k++) { tp += sHit[k]; ang += sAngA[k]; }
        float tpf = (float)tp;
        out[b * 3 + 0] = tpf;
        out[b * 3 + 1] = (float)K - tpf;
        out[b * 3 + 2] = (float)nt - tpf;
        out[3 * NB + b] = (tp > 0) ? (ang / (3.0f * tpf)) : 0.0f;
        // this CTA is provably the last user of batch b's scratch this run
        gDone[b] = 0; gnP[b] = 0; gnT[b] = 0; gMax[b] = 0ull;
    }
}

extern "C" void kernel_launch(void* const* d_in, const int* in_sizes, int n_in,
                              void* d_out, int out_size) {
    const float* pred = (const float*)d_in[0];
    const float* targ = (const float*)d_in[1];
    float* out = (float*)d_out;
    cudaFuncSetAttribute(mol_kernel, cudaFuncAttributeMaxDynamicSharedMemorySize,
                         SMEM_BYTES);
    mol_kernel<<<NB * TILES, T, SMEM_BYTES>>>(pred, targ, out);
}

// round 6
// speedup vs baseline: 1.8276x; 1.8276x over previous
#include <cuda_runtime.h>
#include <math.h>
#include <float.h>

// Problem constants: B=8, Z=4, X=32, Y=32, N=4096
#define NPTS   4096
#define NB     8
#define T      512
#define NW     (T / 32)          // 16 warps
#define CHUNK  512
#define NCH    (NPTS / CHUNK)    // 8 chunks
#define RITER  (NPTS / T)        // 8 points per thread in block scans
#define MAXK   64
#define CUT2   4.0f              // sqrt(ss) < 2  <=>  ss < 4  (exact)

// smem: sP4[4096]*16B + sT4[4096]*16B + staging SP/ST (2 * 5120 floats)
#define SMEM_BYTES (NPTS * 16 * 2 + 2 * CHUNK * 10 * 4)

__device__ __forceinline__ float row_angle(float ax, float ay, float az,
                                           float bx, float by, float bz) {
    float na = sqrtf(ax * ax + ay * ay + az * az);
    float nb = sqrtf(bx * bx + by * by + bz * bz);
    float c = (ax * bx + ay * by + az * bz) / (na * nb);
    c = fminf(1.0f, fmaxf(-1.0f, c));
    return (acosf(c) / 3.14159265358979323846f) * 180.0f;
}

__global__ __launch_bounds__(T, 1)
void mol_kernel(const float* __restrict__ pred,
                const float* __restrict__ targ,
                float* __restrict__ out) {
    extern __shared__ float sm[];
    float4* sP4 = (float4*)sm;              // [NPTS] (x,y,z norm, conf|-FLT_MAX)
    float4* sT4 = sP4 + NPTS;               // [NPTS] (tx,ty,tz real | 1e30 sentinel, -)
    float*  SP  = (float*)(sT4 + NPTS);     // [CHUNK*10] raw pred staging
    float*  ST  = SP + CHUNK * 10;          // [CHUNK*10] raw targ staging
    float*  smf = sm;                       // scalar view of sP4 for .w stores

    __shared__ float wv[NW];
    __shared__ int wiA[NW];
    __shared__ int sK, sSel, sNTG;
    __shared__ float selp[3];
    __shared__ int   kId[MAXK];
    __shared__ float kRX[MAXK], kRY[MAXK], kRZ[MAXK];
    __shared__ int   sMatch[MAXK], sHit[MAXK];
    __shared__ float sAngA[MAXK];

    const int tid = threadIdx.x;
    const int lane = tid & 31;
    const int warp = tid >> 5;
    const int b = blockIdx.x;

    // ---- Phase 1: staged coalesced load (LDG.128) + parse into float4 SoA ----
    int cnt = 0;
    for (int c = 0; c < NCH; c++) {
        const float4* gp4 = (const float4*)(pred + ((size_t)b * NPTS + c * CHUNK) * 10);
        const float4* gt4 = (const float4*)(targ + ((size_t)b * NPTS + c * CHUNK) * 10);
        float4* sp4 = (float4*)SP;
        float4* st4 = (float4*)ST;
        #pragma unroll
        for (int i = tid; i < CHUNK * 10 / 4; i += T) {   // 1280 float4 each
            sp4[i] = gp4[i];
            st4[i] = gt4[i];
        }
        __syncthreads();
        {
            int n = c * CHUNK + tid;
            float fz = (float)(n >> 10), fx = (float)((n >> 5) & 31), fy = (float)(n & 31);
            const float* p = SP + tid * 10;
            const float* t = ST + tid * 10;
            float pc = p[0];
            // sigmoid(conf)>0.5 <=> raw>0 (exact); /4,/32 exact pow2 mults
            sP4[n] = make_float4((p[1] + fz) * 0.25f,
                                 (p[2] + fx) * 0.03125f,
                                 (p[3] + fy) * 0.03125f,
                                 (pc > 0.0f) ? pc : -FLT_MAX);
            bool act = t[0] > 0.5f;
            cnt += act ? 1 : 0;
            // real coords; inactive -> x sentinel makes every distance test fail
            sT4[n] = make_float4(act ? ((t[1] + fz) * 0.25f) * 25.0f : 1e30f,
                                 ((t[2] + fx) * 0.03125f) * 25.0f,
                                 ((t[3] + fy) * 0.03125f) * 4.0f,
                                 0.0f);
        }
        __syncthreads();
    }

    // active-target count
    #pragma unroll
    for (int o = 16; o; o >>= 1) cnt += __shfl_down_sync(0xffffffffu, cnt, o);
    if (lane == 0) wiA[warp] = cnt;
    if (tid == 0) {
        sK = 0;
        selp[0] = 1e30f; selp[1] = 1e30f; selp[2] = 1e30f;   // round 0: no suppression
    }
    __syncthreads();
    if (tid == 0) {
        int s = 0;
        for (int w = 0; w < NW; w++) s += wiA[w];
        sNTG = s;
    }
    __syncthreads();

    // ---- Phase 2: greedy NMS; suppression of previous pick fused into argmax ----
    for (;;) {
        float c0 = selp[0], c1 = selp[1], c2 = selp[2];
        float bv = -FLT_MAX;
        int bi = 0x7fffffff;
        #pragma unroll
        for (int j = 0; j < RITER; j++) {
            int n = j * T + tid;
            float4 q = sP4[n];
            float v = q.w;
            if (v != -FLT_MAX) {
                float d0 = q.x - c0, d1 = q.y - c1, d2 = q.z - c2;
                float ss = (d0 * d0 + d1 * d1) + d2 * d2;
                if (ss < CUT2) { smf[4 * n + 3] = -FLT_MAX; v = -FLT_MAX; }
            }
            if (v > bv) { bv = v; bi = n; }   // ascending n keeps lowest idx on tie
        }
        #pragma unroll
        for (int o = 16; o; o >>= 1) {
            float v2 = __shfl_down_sync(0xffffffffu, bv, o);
            int i2 = __shfl_down_sync(0xffffffffu, bi, o);
            if (v2 > bv || (v2 == bv && i2 < bi)) { bv = v2; bi = i2; }
        }
        if (lane == 0) { wv[warp] = bv; wiA[warp] = bi; }
        __syncthreads();
        if (warp == 0) {
            float v = (lane < NW) ? wv[lane] : -FLT_MAX;
            int i = (lane < NW) ? wiA[lane] : 0x7fffffff;
            #pragma unroll
            for (int o = 8; o; o >>= 1) {
                float v2 = __shfl_down_sync(0xffffffffu, v, o);
                int i2 = __shfl_down_sync(0xffffffffu, i, o);
                if (v2 > v || (v2 == v && i2 < i)) { v = v2; i = i2; }
            }
            if (lane == 0) {
                if (v == -FLT_MAX || sK >= MAXK) {
                    sSel = -1;
                } else {
                    int K = sK;
                    float4 q = sP4[i];
                    kId[K] = i;
                    kRX[K] = q.x * 25.0f; kRY[K] = q.y * 25.0f; kRZ[K] = q.z * 4.0f;
                    selp[0] = q.x; selp[1] = q.y; selp[2] = q.z;
                    sK = K + 1;
                    sSel = i;
                }
            }
        }
        __syncthreads();
        if (sSel < 0) break;
    }

    // ---- Phase 3: matching, warp-parallel — warp w handles kept points w, w+16, ... ----
    const int K = sK;
    for (int k = warp; k < K; k += NW) {
        float qx = kRX[k], qy = kRY[k], qz = kRZ[k];
        int best = 0x7fffffff;
        #pragma unroll 4
        for (int e = lane; e < NPTS; e += 32) {
            float4 q = sT4[e];
            float d0 = q.x - qx, d1 = q.y - qy, d2 = q.z - qz;
            float ss = (d0 * d0 + d1 * d1) + d2 * d2;
            if (ss < CUT2 && e < best) best = e;   // sentinel 1e30 auto-fails
        }
        #pragma unroll
        for (int o = 16; o; o >>= 1) {
            int v2 = __shfl_down_sync(0xffffffffu, best, o);
            if (v2 < best) best = v2;
        }
        if (lane == 0) sMatch[k] = best;
    }
    __syncthreads();

    // ---- Phase 4: K parallel angle computations (global reads, L2-hot, 8B aligned) ----
    if (tid < K) {
        int mt = sMatch[tid];
        if (mt != 0x7fffffff) {
            const float* p = pred + ((size_t)b * NPTS + kId[tid]) * 10 + 4;
            const float* t = targ + ((size_t)b * NPTS + mt) * 10 + 4;
            float2 pa2 = *(const float2*)p;
            float2 pb2 = *(const float2*)(p + 2);
            float2 pc2 = *(const float2*)(p + 4);
            float2 ta2 = *(const float2*)t;
            float2 tb2 = *(const float2*)(t + 2);
            float2 tc2 = *(const float2*)(t + 4);
            float ax = pa2.x, ay = pa2.y, az = pb2.x;
            float bx = pb2.y, by = pc2.x, bz = pc2.y;
            float cx = ay * bz - az * by;
            float cy = az * bx - ax * bz;
            float cz = ax * by - ay * bx;
            float tax = ta2.x, tay = ta2.y, taz = tb2.x;
            float tbx = tb2.y, tby = tc2.x, tbz = tc2.y;
            float tcx = tay * tbz - taz * tby;
            float tcy = taz * tbx - tax * tbz;
            float tcz = tax * tby - tay * tbx;
            sAngA[tid] = row_angle(ax, ay, az, tax, tay, taz)
                       + row_angle(bx, by, bz, tbx, tby, tbz)
                       + row_angle(cx, cy, cz, tcx, tcy, tcz);
            sHit[tid] = 1;
        } else {
            sAngA[tid] = 0.0f;
            sHit[tid] = 0;
        }
    }
    __syncthreads();

    // ---- Phase 5: deterministic epilogue ----
    if (tid == 0) {
        int tp = 0;
        float ang = 0.0f;
        for (int k = 0; k < K; k++) { tp += sHit[k]; ang += sAngA[k]; }
        float tpf = (float)tp;
        out[b * 3 + 0] = tpf;
        out[b * 3 + 1] = (float)K - tpf;
        out[b * 3 + 2] = (float)sNTG - tpf;
        out[3 * NB + b] = (tp > 0) ? (ang / (3.0f * tpf)) : 0.0f;
    }
}

extern "C" void kernel_launch(void* const* d_in, const int* in_sizes, int n_in,
                              void* d_out, int out_size) {
    const float* pred = (const float*)d_in[0];
    const float* targ = (const float*)d_in[1];
    float* out = (float*)d_out;
    cudaFuncSetAttribute(mol_kernel, cudaFuncAttributeMaxDynamicSharedMemorySize,
                         SMEM_BYTES);
    mol_kernel<<<NB, T, SMEM_BYTES>>>(pred, targ, out);
}